// round 12
// baseline (speedup 1.0000x reference)
#include <cuda_runtime.h>
#include <cooperative_groups.h>
#include <cstdint>

namespace cg = cooperative_groups;

#define IMGS 8
#define HH 1024
#define WPX 1024
#define WW 32            // 32-bit words per row
#define WP 33            // padded row stride (bank-conflict-free)
#define MAXIT 64

// Static global scratch (no allocations allowed)
__device__ uint32_t g_cbits[IMGS][HH][WW];    // endpoint bits (1 MB)
__device__ int      g_flag[IMGS * MAXIT];     // per-image per-iteration changed flags
__device__ double   g_partial[1024];          // block partial sums
__device__ int      g_count;                  // finished-block counter for k_loss

// ---------------------------------------------------------------------------
// helpers
// ---------------------------------------------------------------------------
__device__ __forceinline__ uint32_t shW(uint32_t l, uint32_t m) {
    return __funnelshift_l(l, m, 1);     // west neighbor mask
}
__device__ __forceinline__ uint32_t shE(uint32_t m, uint32_t r) {
    return __funnelshift_r(m, r, 1);     // east neighbor mask
}

struct Bn4 { uint32_t n0, n1, n2, n3; };

__device__ __forceinline__ Bn4 bn8(uint32_t P2, uint32_t P3, uint32_t P4, uint32_t P5,
                                   uint32_t P6, uint32_t P7, uint32_t P8, uint32_t P9) {
    uint32_t s1 = P2 ^ P3 ^ P4, k1 = (P2 & P3) | (P4 & (P2 | P3));
    uint32_t s2 = P5 ^ P6 ^ P7, k2 = (P5 & P6) | (P7 & (P5 | P6));
    uint32_t s3 = s1 ^ s2 ^ P8, k3 = (s1 & s2) | (P8 & (s1 | s2));
    uint32_t n0 = s3 ^ P9,      k4 = s3 & P9;
    uint32_t s4 = k1 ^ k2 ^ k3, k5 = (k1 & k2) | (k3 & (k1 | k2));
    uint32_t n1 = s4 ^ k4,      k6 = s4 & k4;
    Bn4 r; r.n0 = n0; r.n1 = n1; r.n2 = k5 ^ k6; r.n3 = k5 & k6; return r;
}

// per-word Zhang-Suen decision (shared by 4-word and 8-word paths)
template <int SUB>
__device__ __forceinline__ uint32_t zs_word(uint32_t aL, uint32_t aM, uint32_t aR,
                                            uint32_t cL, uint32_t cM, uint32_t cR,
                                            uint32_t bL, uint32_t bM, uint32_t bR) {
    uint32_t P2 = aM, P6 = bM;
    uint32_t P3 = shE(aM, aR), P4 = shE(cM, cR), P5 = shE(bM, bR);
    uint32_t P7 = shW(bL, bM), P8 = shW(cL, cM), P9 = shW(aL, aM);
    Bn4 n = bn8(P2, P3, P4, P5, P6, P7, P8, P9);
    uint32_t ge2 = n.n1 | n.n2 | n.n3;
    uint32_t ge7 = n.n3 | (n.n0 & n.n1 & n.n2);
    uint32_t condB = ge2 & ~ge7;
    uint32_t t, acc, multi;
    acc = ~P2 & P3; multi = 0u;
    t = ~P3 & P4; multi |= acc & t; acc |= t;
    t = ~P4 & P5; multi |= acc & t; acc |= t;
    t = ~P5 & P6; multi |= acc & t; acc |= t;
    t = ~P6 & P7; multi |= acc & t; acc |= t;
    t = ~P7 & P8; multi |= acc & t; acc |= t;
    t = ~P8 & P9; multi |= acc & t; acc |= t;
    t = ~P9 & P2; multi |= acc & t; acc |= t;
    uint32_t A1 = acc & ~multi;
    uint32_t e1, e2;
    if (SUB == 0) { e1 = ~(P2 & P4 & P6); e2 = ~(P4 & P6 & P8); }
    else          { e1 = ~(P2 & P4 & P8); e2 = ~(P2 & P6 & P8); }
    return cM & condB & A1 & e1 & e2;   // removal mask
}

// 4-word-per-thread substep. orig != nullptr -> ch = orig ^ newval (else rem).
template <int SUB>
__device__ __forceinline__ uint32_t thin4(const uint32_t* __restrict__ rowA,
                                          const uint32_t* __restrict__ rowC,
                                          const uint32_t* __restrict__ rowB,
                                          uint32_t* __restrict__ dst,
                                          const uint32_t* __restrict__ orig,
                                          int w0) {
    uint32_t a[6], c[6], b[6];
    #pragma unroll
    for (int i = 0; i < 6; ++i) {
        int w = w0 - 1 + i;
        bool ok = (w >= 0) && (w < WW);
        a[i] = ok ? rowA[w] : 0u;
        c[i] = ok ? rowC[w] : 0u;
        b[i] = ok ? rowB[w] : 0u;
    }
    uint32_t ch = 0;
    #pragma unroll
    for (int i = 0; i < 4; ++i) {
        uint32_t rem = zs_word<SUB>(a[i], a[i+1], a[i+2], c[i], c[i+1], c[i+2],
                                    b[i], b[i+1], b[i+2]);
        uint32_t newv = c[i+1] ^ rem;
        dst[w0 + i] = newv;
        ch |= orig ? (orig[w0 + i] ^ newv) : rem;
    }
    return ch;
}

__device__ __forceinline__ void endpoint4(const uint32_t* __restrict__ rowA,
                                          const uint32_t* __restrict__ rowC,
                                          const uint32_t* __restrict__ rowB,
                                          int img, int gy, int w0) {
    uint32_t a[6], c[6], b[6];
    #pragma unroll
    for (int i = 0; i < 6; ++i) {
        int w = w0 - 1 + i;
        bool ok = (w >= 0) && (w < WW);
        a[i] = ok ? rowA[w] : 0u;
        c[i] = ok ? rowC[w] : 0u;
        b[i] = ok ? rowB[w] : 0u;
    }
    #pragma unroll
    for (int i = 0; i < 4; ++i) {
        uint32_t P2 = a[i+1], P6 = b[i+1];
        uint32_t P3 = shE(a[i+1], a[i+2]), P4 = shE(c[i+1], c[i+2]), P5 = shE(b[i+1], b[i+2]);
        uint32_t P7 = shW(b[i], b[i+1]), P8 = shW(c[i], c[i+1]), P9 = shW(a[i], a[i+1]);
        Bn4 n = bn8(P2, P3, P4, P5, P6, P7, P8, P9);
        g_cbits[img][gy][w0 + i] = c[i+1] & n.n0 & ~(n.n1 | n.n2 | n.n3);
    }
}

// ---------------------------------------------------------------------------
// NEW 16-CTA thinning: fat iterations (both substeps locally), ONE
// cluster.sync per iteration, double-buffered state, 512 threads/CTA.
// ---------------------------------------------------------------------------
#define TROWS 64
struct ThinSmem16 {
    uint32_t img0[2][TROWS][WP];   // ping-pong state buffers (halo-read by peers)
    uint32_t img1[TROWS + 2][WP];  // local extended sub0 result (rows -1..TROWS)
    uint32_t zero[WP];
    uint8_t  rowch[2][TROWS];      // per-iteration change flags (peer-read ±2)
    int      sflag;
};

__global__ void __cluster_dims__(16, 1, 1) __launch_bounds__(512, 1)
k_thin16(const float* __restrict__ pred) {
    __shared__ ThinSmem16 sm;
    cg::cluster_group cluster = cg::this_cluster();
    const int tid  = threadIdx.x;
    const int lane = tid & 31;
    const int warp = tid >> 5;
    const int rank = (int)cluster.block_rank();
    const int img  = blockIdx.x >> 4;
    int* flag = &g_flag[img * MAXIT];

    // ---- pack: threshold pred into img0[0] (float4 + shfl-OR), 16 warps ----
    for (int r = warp; r < TROWS; r += 16) {
        const float4* row = (const float4*)(pred + ((size_t)img * HH + (size_t)rank * TROWS + r) * WPX);
        #pragma unroll
        for (int step = 0; step < 8; ++step) {
            float4 v = row[step * 32 + lane];
            uint32_t nib = (v.x >= 0.5f ? 1u : 0u) | (v.y >= 0.5f ? 2u : 0u)
                         | (v.z >= 0.5f ? 4u : 0u) | (v.w >= 0.5f ? 8u : 0u);
            uint32_t x = nib << (4 * (lane & 7));
            x |= __shfl_xor_sync(0xffffffffu, x, 1);
            x |= __shfl_xor_sync(0xffffffffu, x, 2);
            x |= __shfl_xor_sync(0xffffffffu, x, 4);
            if ((lane & 7) == 0) sm.img0[0][r][step * 4 + (lane >> 3)] = x;
        }
    }
    if (tid < WP) sm.zero[tid] = 0u;
    if (rank == 0) { for (int i = tid; i < MAXIT; i += 512) flag[i] = 0; }
    if (blockIdx.x == 0 && tid == 0) g_count = 0;
    __threadfence();
    cluster.sync();

    ThinSmem16* pprev = (rank > 0)  ? (ThinSmem16*)cluster.map_shared_rank(&sm, rank - 1) : nullptr;
    ThinSmem16* pnext = (rank < 15) ? (ThinSmem16*)cluster.map_shared_rank(&sm, rank + 1) : nullptr;

    const int my = tid >> 3;          // my row 0..63
    const int w0 = (tid & 7) * 4;     // 4-word group

    int src = 0;
    int iter = 0;
    for (; iter < MAXIT; ++iter) {
        const int pb = (iter + 1) & 1;   // prev-iteration rowch buffer
        const int cb = iter & 1;         // current rowch buffer
        const int dst = src ^ 1;
        if (tid == 0) sm.sflag = 0;

        // virtual accessors over CTA-local coords (may reach into peers)
        auto row0 = [&](int v) -> const uint32_t* {
            if (v >= 0 && v < TROWS) return sm.img0[src][v];
            if (v < 0) return pprev ? pprev->img0[src][TROWS + v] : sm.zero;
            return pnext ? pnext->img0[src][v - TROWS] : sm.zero;
        };
        auto prch = [&](int v) -> unsigned {
            if (v >= 0 && v < TROWS) return sm.rowch[pb][v];
            if (v < 0) return pprev ? (unsigned)pprev->rowch[pb][TROWS + v] : 0u;
            return pnext ? (unsigned)pnext->rowch[pb][v - TROWS] : 0u;
        };

        // ---- substep 0 over extended rows e = -1..TROWS -> img1[e+1] ----
        for (int ee = my; ee < TROWS + 2; ee += TROWS) {
            int e = ee - 1;
            bool recompute = true;
            if (iter > 0) recompute = (prch(e - 1) | prch(e) | prch(e + 1)) != 0u;
            if (recompute)
                thin4<0>(row0(e - 1), row0(e), row0(e + 1), sm.img1[ee], nullptr, w0);
        }
        __syncthreads();   // img1 complete CTA-locally; also orders sflag reset

        // ---- substep 1 for my row -> img0[dst][my]; ch = orig ^ final ----
        {
            bool recompute = true;
            if (iter > 0)
                recompute = (prch(my - 2) | prch(my - 1) | prch(my) |
                             prch(my + 1) | prch(my + 2)) != 0u;
            uint32_t ch = 0;
            if (recompute)
                ch = thin4<1>(sm.img1[my], sm.img1[my + 1], sm.img1[my + 2],
                              sm.img0[dst][my], sm.img0[src][my], w0);
            unsigned bal = __ballot_sync(0xffffffffu, ch != 0u);
            if ((tid & 7) == 0)
                sm.rowch[cb][my] = (uint8_t)(((bal >> (lane & 24)) & 0xFFu) ? 1 : 0);
            if (bal && lane == 0) sm.sflag = 1;
        }
        __syncthreads();
        if (tid == 0 && sm.sflag) { atomicOr(&flag[iter], 1); __threadfence(); }
        cluster.sync();                   // publish img0[dst], rowch, flag
        src ^= 1;
        if (__ldcg(&flag[iter]) == 0) break;   // uniform across the cluster
    }

    // ---- fused endpoint extraction from img0[src] ----
    {
        const uint32_t* rA = (my > 0) ? sm.img0[src][my - 1]
                          : (pprev ? pprev->img0[src][TROWS - 1] : sm.zero);
        const uint32_t* rB = (my < TROWS - 1) ? sm.img0[src][my + 1]
                          : (pnext ? pnext->img0[src][0] : sm.zero);
        endpoint4(rA, sm.img0[src][my], rB, img, rank * TROWS + my, w0);
    }
    cluster.sync();   // no CTA exits while peers may still read its smem
}

// ---------------------------------------------------------------------------
// Fallback 8-CTA thinning: proven old code (2 syncs/iter, 8 words/thread)
// ---------------------------------------------------------------------------
template <int SUB>
__device__ __forceinline__ uint32_t thin_rows(const uint32_t* __restrict__ rowA,
                                              const uint32_t* __restrict__ rowC,
                                              const uint32_t* __restrict__ rowB,
                                              uint32_t* __restrict__ dst, int w0) {
    uint32_t a[10], c[10], b[10];
    #pragma unroll
    for (int i = 0; i < 10; ++i) {
        int w = w0 - 1 + i;
        bool ok = (w >= 0) && (w < WW);
        a[i] = ok ? rowA[w] : 0u;
        c[i] = ok ? rowC[w] : 0u;
        b[i] = ok ? rowB[w] : 0u;
    }
    uint32_t ch = 0;
    #pragma unroll
    for (int i = 0; i < 8; ++i) {
        uint32_t rem = zs_word<SUB>(a[i], a[i+1], a[i+2], c[i], c[i+1], c[i+2],
                                    b[i], b[i+1], b[i+2]);
        dst[w0 + i] = c[i+1] ^ rem;
        ch |= rem;
    }
    return ch;
}

struct ThinSmem8 {
    uint32_t img[2][128][WP];
    uint32_t zero[WP];
    uint8_t  rowch[3][128];
    int      sflag;
};

__global__ void __cluster_dims__(8, 1, 1) __launch_bounds__(512, 1)
k_thin8(const float* __restrict__ pred) {
    __shared__ ThinSmem8 sm;
    cg::cluster_group cluster = cg::this_cluster();
    const int tid = threadIdx.x, lane = tid & 31, warp = tid >> 5;
    const int rank = (int)cluster.block_rank();
    const int img = blockIdx.x >> 3;
    int* flag = &g_flag[img * MAXIT];
    const int ROWS = 128;

    for (int r = warp; r < ROWS; r += 16) {
        const float4* row = (const float4*)(pred + ((size_t)img * HH + (size_t)rank * ROWS + r) * WPX);
        #pragma unroll
        for (int step = 0; step < 8; ++step) {
            float4 v = row[step * 32 + lane];
            uint32_t nib = (v.x >= 0.5f ? 1u : 0u) | (v.y >= 0.5f ? 2u : 0u)
                         | (v.z >= 0.5f ? 4u : 0u) | (v.w >= 0.5f ? 8u : 0u);
            uint32_t x = nib << (4 * (lane & 7));
            x |= __shfl_xor_sync(0xffffffffu, x, 1);
            x |= __shfl_xor_sync(0xffffffffu, x, 2);
            x |= __shfl_xor_sync(0xffffffffu, x, 4);
            if ((lane & 7) == 0) sm.img[0][r][step * 4 + (lane >> 3)] = x;
        }
    }
    if (tid < WP) sm.zero[tid] = 0u;
    if (rank == 0) { for (int i = tid; i < MAXIT; i += 512) flag[i] = 0; }
    if (blockIdx.x == 0 && tid == 0) g_count = 0;
    __threadfence();
    cluster.sync();

    ThinSmem8* pprev = (rank > 0) ? (ThinSmem8*)cluster.map_shared_rank(&sm, rank - 1) : nullptr;
    ThinSmem8* pnext = (rank < 7) ? (ThinSmem8*)cluster.map_shared_rank(&sm, rank + 1) : nullptr;
    const int ly = tid >> 2, w0 = (tid & 3) * 8;

    int cur = 0;
    for (int iter = 0; iter < MAXIT; ++iter) {
        if (tid == 0) sm.sflag = 0;
        __syncthreads();
        #pragma unroll
        for (int sub = 0; sub < 2; ++sub) {
            bool recompute = true;
            if (iter > 0) {
                int p1 = (cur + 2) % 3, p2 = (cur + 1) % 3;
                unsigned d = (unsigned)sm.rowch[p1][ly] | (unsigned)sm.rowch[p2][ly];
                if (ly > 0)        d |= (unsigned)sm.rowch[p1][ly-1] | (unsigned)sm.rowch[p2][ly-1];
                else if (pprev)    d |= (unsigned)pprev->rowch[p1][ROWS-1] | (unsigned)pprev->rowch[p2][ROWS-1];
                if (ly < ROWS - 1) d |= (unsigned)sm.rowch[p1][ly+1] | (unsigned)sm.rowch[p2][ly+1];
                else if (pnext)    d |= (unsigned)pnext->rowch[p1][0] | (unsigned)pnext->rowch[p2][0];
                recompute = (d != 0u);
            }
            uint32_t ch = 0;
            int s = sub, d2 = sub ^ 1;
            if (recompute) {
                const uint32_t* rA = (ly > 0) ? sm.img[s][ly-1]
                                  : (pprev ? pprev->img[s][ROWS-1] : sm.zero);
                const uint32_t* rB = (ly < ROWS - 1) ? sm.img[s][ly+1]
                                  : (pnext ? pnext->img[s][0] : sm.zero);
                ch = (sub == 0) ? thin_rows<0>(rA, sm.img[s][ly], rB, sm.img[d2][ly], w0)
                                : thin_rows<1>(rA, sm.img[s][ly], rB, sm.img[d2][ly], w0);
            }
            unsigned bal = __ballot_sync(0xffffffffu, ch != 0u);
            if ((tid & 3) == 0)
                sm.rowch[cur][ly] = (uint8_t)(((bal >> (lane & 28)) & 0xFu) ? 1 : 0);
            if (bal && lane == 0) sm.sflag = 1;
            if (sub == 0) cluster.sync();
            cur = (cur + 1) % 3;
        }
        __syncthreads();
        if (tid == 0 && sm.sflag) { atomicOr(&flag[iter], 1); __threadfence(); }
        cluster.sync();
        if (__ldcg(&flag[iter]) == 0) break;
    }

    {
        const uint32_t* rA = (ly > 0) ? sm.img[0][ly-1]
                          : (pprev ? pprev->img[0][ROWS-1] : sm.zero);
        const uint32_t* rB = (ly < ROWS - 1) ? sm.img[0][ly+1]
                          : (pnext ? pnext->img[0][0] : sm.zero);
        endpoint4(rA, sm.img[0][ly], rB, img, rank * ROWS + ly, (tid & 3) * 8);
        endpoint4(rA, sm.img[0][ly], rB, img, rank * ROWS + ly, (tid & 3) * 8 + 4);
    }
    cluster.sync();
}

// ---------------------------------------------------------------------------
// K2: weight + BCE with DECOUPLED layouts (round-11 proven version, unchanged)
// ---------------------------------------------------------------------------
#define FA3(a, b, c, s, cy) { uint32_t _x = (a) ^ (b); (s) = _x ^ (c); (cy) = ((a) & (b)) | ((c) & _x); }

__global__ void __launch_bounds__(256) k_loss(const float* __restrict__ pred,
                                              const float* __restrict__ targ,
                                              float* __restrict__ out) {
    const int tid = threadIdx.x;
    const int img = blockIdx.x >> 7;
    const int y0  = (blockIdx.x & 127) * 8;
    const uint32_t* C = &g_cbits[img][0][0];

    __shared__ uint32_t tile[16][WW + 1];
    __shared__ uint32_t splanes[256 * 9];
    #pragma unroll
    for (int k = 0; k < 2; ++k) {
        int idx = tid + k * 256;
        int sr = idx >> 5, sw = idx & 31;
        int gy = y0 - 4 + sr;
        tile[sr][sw] = (gy >= 0 && gy < HH) ? C[gy * WW + sw] : 0u;
    }
    __syncthreads();

    {
        const int w = tid & 31, lr = tid >> 5;
        uint32_t rlo[9], rhi[9], orAll = 0;
        #pragma unroll
        for (int d = 0; d < 9; ++d) {
            uint32_t M = tile[lr + d][w];
            uint32_t L = (w > 0)  ? tile[lr + d][w - 1] : 0u;
            uint32_t R = (w < 31) ? tile[lr + d][w + 1] : 0u;
            rlo[d] = (L >> 28) | (M << 4);
            rhi[d] = (M >> 28) | ((R & 0xFu) << 4);
            orAll |= rlo[d] | rhi[d];
        }
        uint32_t* P = &splanes[tid * 9];
        if (orAll) {
            uint32_t s1, c1, s2, c2, s3, c3, c4, s5, c5, c6;
            FA3(rlo[0], rlo[1], rlo[2], s1, c1);
            FA3(rlo[3], rlo[4], rlo[5], s2, c2);
            FA3(rlo[6], rlo[7], rlo[8], s3, c3);
            uint32_t S0l, S1l, S2l, S3l;
            FA3(s1, s2, s3, S0l, c4);
            FA3(c1, c2, c3, s5, c5);
            S1l = s5 ^ c4; c6 = s5 & c4;
            S2l = c5 ^ c6; S3l = c5 & c6;
            P[0] = S0l; P[1] = S1l; P[2] = S2l; P[3] = S3l;
            FA3(rhi[0], rhi[1], rhi[2], s1, c1);
            FA3(rhi[3], rhi[4], rhi[5], s2, c2);
            FA3(rhi[6], rhi[7], rhi[8], s3, c3);
            uint32_t S0h, S1h, S2h, S3h;
            FA3(s1, s2, s3, S0h, c4);
            FA3(c1, c2, c3, s5, c5);
            S1h = s5 ^ c4; c6 = s5 & c4;
            S2h = c5 ^ c6; S3h = c5 & c6;
            P[4] = S0h; P[5] = S1h; P[6] = S2h; P[7] = S3h;
        }
        P[8] = orAll;
    }
    __syncthreads();

    const float4* p4 = (const float4*)pred + (size_t)blockIdx.x * 2048;
    const float4* t4 = (const float4*)targ + (size_t)blockIdx.x * 2048;
    const int kbase = (tid & 7) * 4;
    float fsum = 0.0f;

    float4 pv = __ldcs(p4 + tid), tv = __ldcs(t4 + tid);
    #pragma unroll
    for (int p = 0; p < 8; ++p) {
        float4 pn, tn;
        if (p < 7) { pn = __ldcs(p4 + (p + 1) * 256 + tid); tn = __ldcs(t4 + (p + 1) * 256 + tid); }
        const uint32_t* P = &splanes[(p * 32 + (tid >> 3)) * 9];
        uint32_t cov = P[8];
        float pa[4] = {pv.x, pv.y, pv.z, pv.w};
        float ta[4] = {tv.x, tv.y, tv.z, tv.w};
        #pragma unroll
        for (int j = 0; j < 4; ++j) {
            float pp = pa[j], tt = ta[j];
            float Lb = -(tt * __logf(pp) + (1.0f - tt) * __logf(1.0f - pp));
            float Wt = 1.0f;
            if (cov) {
                int k = kbase + j;
                int nsum = __popc(__funnelshift_r(P[0], P[4], k) & 0x1FFu)
                         + (__popc(__funnelshift_r(P[1], P[5], k) & 0x1FFu) << 1)
                         + (__popc(__funnelshift_r(P[2], P[6], k) & 0x1FFu) << 2)
                         + (__popc(__funnelshift_r(P[3], P[7], k) & 0x1FFu) << 3);
                if (nsum) Wt = 60.0f * (float)nsum;
            }
            fsum += Wt * Lb;
        }
        pv = pn; tv = tn;
    }

    __shared__ double sd[256];
    sd[tid] = (double)fsum;
    __syncthreads();
    #pragma unroll
    for (int s = 128; s > 0; s >>= 1) {
        if (tid < s) sd[tid] += sd[tid + s];
        __syncthreads();
    }
    __shared__ int slast;
    if (tid == 0) {
        g_partial[blockIdx.x] = sd[0];
        __threadfence();
        slast = (atomicAdd(&g_count, 1) == (int)gridDim.x - 1);
    }
    __syncthreads();
    if (!slast) return;

    double v = __ldcg(&g_partial[tid]) + __ldcg(&g_partial[tid + 256])
             + __ldcg(&g_partial[tid + 512]) + __ldcg(&g_partial[tid + 768]);
    sd[tid] = v;
    __syncthreads();
    #pragma unroll
    for (int s = 128; s > 0; s >>= 1) {
        if (tid < s) sd[tid] += sd[tid + s];
        __syncthreads();
    }
    if (tid == 0) out[0] = (float)(sd[0] * (1.0 / ((double)IMGS * HH * WPX)));
}

// ---------------------------------------------------------------------------
extern "C" void kernel_launch(void* const* d_in, const int* in_sizes, int n_in,
                              void* d_out, int out_size) {
    (void)in_sizes; (void)n_in; (void)out_size;
    const float* pred = (const float*)d_in[0];
    const float* targ = (const float*)d_in[1];
    float* out = (float*)d_out;

    cudaError_t e = cudaFuncSetAttribute(
        (const void*)k_thin16, cudaFuncAttributeNonPortableClusterSizeAllowed, 1);
    if (e == cudaSuccess) {
        k_thin16<<<128, 512>>>(pred);
    } else {
        (void)cudaGetLastError();   // clear sticky error before capture continues
        k_thin8<<<64, 512>>>(pred);
    }

    k_loss<<<1024, 256>>>(pred, targ, out);
}

// round 13
// speedup vs baseline: 1.0645x; 1.0645x over previous
#include <cuda_runtime.h>
#include <cooperative_groups.h>
#include <cstdint>

namespace cg = cooperative_groups;

#define IMGS 8
#define HH 1024
#define WPX 1024
#define WW 32            // 32-bit words per row
#define WP 33            // padded row stride (bank-conflict-free)
#define MAXIT 64

// Static global scratch (no allocations allowed)
__device__ uint32_t g_cbits[IMGS][HH][WW];    // endpoint bits (1 MB)
__device__ int      g_flag[IMGS * MAXIT];     // per-image per-iteration changed flags
__device__ double   g_partial[1024];          // block partial sums
__device__ int      g_count;                  // finished-block counter for k_loss

// ---------------------------------------------------------------------------
// helpers
// ---------------------------------------------------------------------------
__device__ __forceinline__ uint32_t shW(uint32_t l, uint32_t m) {
    return __funnelshift_l(l, m, 1);     // west neighbor mask
}
__device__ __forceinline__ uint32_t shE(uint32_t m, uint32_t r) {
    return __funnelshift_r(m, r, 1);     // east neighbor mask
}

struct Bn4 { uint32_t n0, n1, n2, n3; };

__device__ __forceinline__ Bn4 bn8(uint32_t P2, uint32_t P3, uint32_t P4, uint32_t P5,
                                   uint32_t P6, uint32_t P7, uint32_t P8, uint32_t P9) {
    uint32_t s1 = P2 ^ P3 ^ P4, k1 = (P2 & P3) | (P4 & (P2 | P3));
    uint32_t s2 = P5 ^ P6 ^ P7, k2 = (P5 & P6) | (P7 & (P5 | P6));
    uint32_t s3 = s1 ^ s2 ^ P8, k3 = (s1 & s2) | (P8 & (s1 | s2));
    uint32_t n0 = s3 ^ P9,      k4 = s3 & P9;
    uint32_t s4 = k1 ^ k2 ^ k3, k5 = (k1 & k2) | (k3 & (k1 | k2));
    uint32_t n1 = s4 ^ k4,      k6 = s4 & k4;
    Bn4 r; r.n0 = n0; r.n1 = n1; r.n2 = k5 ^ k6; r.n3 = k5 & k6; return r;
}

// per-word Zhang-Suen removal decision
template <int SUB>
__device__ __forceinline__ uint32_t zs_word(uint32_t aL, uint32_t aM, uint32_t aR,
                                            uint32_t cL, uint32_t cM, uint32_t cR,
                                            uint32_t bL, uint32_t bM, uint32_t bR) {
    uint32_t P2 = aM, P6 = bM;
    uint32_t P3 = shE(aM, aR), P4 = shE(cM, cR), P5 = shE(bM, bR);
    uint32_t P7 = shW(bL, bM), P8 = shW(cL, cM), P9 = shW(aL, aM);
    Bn4 n = bn8(P2, P3, P4, P5, P6, P7, P8, P9);
    uint32_t ge2 = n.n1 | n.n2 | n.n3;
    uint32_t ge7 = n.n3 | (n.n0 & n.n1 & n.n2);
    uint32_t condB = ge2 & ~ge7;
    uint32_t t, acc, multi;
    acc = ~P2 & P3; multi = 0u;
    t = ~P3 & P4; multi |= acc & t; acc |= t;
    t = ~P4 & P5; multi |= acc & t; acc |= t;
    t = ~P5 & P6; multi |= acc & t; acc |= t;
    t = ~P6 & P7; multi |= acc & t; acc |= t;
    t = ~P7 & P8; multi |= acc & t; acc |= t;
    t = ~P8 & P9; multi |= acc & t; acc |= t;
    t = ~P9 & P2; multi |= acc & t; acc |= t;
    uint32_t A1 = acc & ~multi;
    uint32_t e1, e2;
    if (SUB == 0) { e1 = ~(P2 & P4 & P6); e2 = ~(P4 & P6 & P8); }
    else          { e1 = ~(P2 & P4 & P8); e2 = ~(P2 & P6 & P8); }
    return cM & condB & A1 & e1 & e2;
}

// NW-word-per-thread substep (returns removal OR)
template <int SUB, int NW>
__device__ __forceinline__ uint32_t thinN(const uint32_t* __restrict__ rowA,
                                          const uint32_t* __restrict__ rowC,
                                          const uint32_t* __restrict__ rowB,
                                          uint32_t* __restrict__ dst, int w0) {
    uint32_t a[NW + 2], c[NW + 2], b[NW + 2];
    #pragma unroll
    for (int i = 0; i < NW + 2; ++i) {
        int w = w0 - 1 + i;
        bool ok = (w >= 0) && (w < WW);
        a[i] = ok ? rowA[w] : 0u;
        c[i] = ok ? rowC[w] : 0u;
        b[i] = ok ? rowB[w] : 0u;
    }
    uint32_t ch = 0;
    #pragma unroll
    for (int i = 0; i < NW; ++i) {
        uint32_t rem = zs_word<SUB>(a[i], a[i+1], a[i+2], c[i], c[i+1], c[i+2],
                                    b[i], b[i+1], b[i+2]);
        dst[w0 + i] = c[i+1] ^ rem;
        ch |= rem;
    }
    return ch;
}

template <int NW>
__device__ __forceinline__ void endpointN(const uint32_t* __restrict__ rowA,
                                          const uint32_t* __restrict__ rowC,
                                          const uint32_t* __restrict__ rowB,
                                          int img, int gy, int w0) {
    uint32_t a[NW + 2], c[NW + 2], b[NW + 2];
    #pragma unroll
    for (int i = 0; i < NW + 2; ++i) {
        int w = w0 - 1 + i;
        bool ok = (w >= 0) && (w < WW);
        a[i] = ok ? rowA[w] : 0u;
        c[i] = ok ? rowC[w] : 0u;
        b[i] = ok ? rowB[w] : 0u;
    }
    #pragma unroll
    for (int i = 0; i < NW; ++i) {
        uint32_t P2 = a[i+1], P6 = b[i+1];
        uint32_t P3 = shE(a[i+1], a[i+2]), P4 = shE(c[i+1], c[i+2]), P5 = shE(b[i+1], b[i+2]);
        uint32_t P7 = shW(b[i], b[i+1]), P8 = shW(c[i], c[i+1]), P9 = shW(a[i], a[i+1]);
        Bn4 n = bn8(P2, P3, P4, P5, P6, P7, P8, P9);
        g_cbits[img][gy][w0 + i] = c[i+1] & n.n0 & ~(n.n1 | n.n2 | n.n3);
    }
}

// ---------------------------------------------------------------------------
// SMEM-resident cluster thinning: proven R5/R11 STRUCTURE (2 cluster.syncs per
// iteration, triple rowch, global flags). Parameterized thread layout:
// TPR threads per row, NWRD = WW/TPR words per thread.
// ---------------------------------------------------------------------------
template <int ROWS>
struct ThinSmem {
    uint32_t img[2][ROWS][WP];   // ping-pong tiles, padded stride
    uint32_t zero[WP];
    uint8_t  rowch[3][ROWS];     // rolling per-row change flags
    int      sflag;
};

template <int NC, int ROWS, int NTHR, int TPR, typename SM>
__device__ void thin_main(SM* sm, const float* __restrict__ pred) {
    constexpr int NWRD = WW / TPR;            // words per thread
    cg::cluster_group cluster = cg::this_cluster();
    const int tid  = threadIdx.x;
    const int lane = tid & 31;
    const int warp = tid >> 5;
    const int rank = (int)cluster.block_rank();
    const int img  = blockIdx.x / NC;
    int* flag = &g_flag[img * MAXIT];

    // ---- pack phase: threshold pred into sm->img[0] (float4 + shfl-OR) ----
    constexpr int NWARP = NTHR / 32;
    for (int r = warp; r < ROWS; r += NWARP) {
        const float4* row = (const float4*)(pred + ((size_t)img * HH + (size_t)rank * ROWS + r) * WPX);
        #pragma unroll
        for (int step = 0; step < 8; ++step) {
            float4 v = row[step * 32 + lane];
            uint32_t nib = (v.x >= 0.5f ? 1u : 0u) | (v.y >= 0.5f ? 2u : 0u)
                         | (v.z >= 0.5f ? 4u : 0u) | (v.w >= 0.5f ? 8u : 0u);
            uint32_t x = nib << (4 * (lane & 7));
            x |= __shfl_xor_sync(0xffffffffu, x, 1);
            x |= __shfl_xor_sync(0xffffffffu, x, 2);
            x |= __shfl_xor_sync(0xffffffffu, x, 4);
            if ((lane & 7) == 0) sm->img[0][r][step * 4 + (lane >> 3)] = x;
        }
    }
    if (tid < WP) sm->zero[tid] = 0u;
    if (rank == 0) { for (int i = tid; i < MAXIT; i += NTHR) flag[i] = 0; }
    if (blockIdx.x == 0 && tid == 0) g_count = 0;
    __threadfence();
    cluster.sync();

    SM* pprev = (rank > 0)      ? (SM*)cluster.map_shared_rank(sm, rank - 1) : nullptr;
    SM* pnext = (rank < NC - 1) ? (SM*)cluster.map_shared_rank(sm, rank + 1) : nullptr;

    const int ly = tid / TPR;                 // local row
    const int w0 = (tid % TPR) * NWRD;        // word group
    // mask/shift for extracting this row's lanes from the ballot
    constexpr unsigned ROWMASK = (TPR >= 32) ? 0xFFFFFFFFu : ((1u << TPR) - 1u);
    const int rowsh = (lane / TPR) * TPR;

    int cur = 0;
    for (int iter = 0; iter < MAXIT; ++iter) {
        if (tid == 0) sm->sflag = 0;
        __syncthreads();

        // ---- substep 0: img[0] -> img[1] ----
        {
            bool recompute = true;
            if (iter > 0) {
                int p1 = (cur + 2) % 3, p2 = (cur + 1) % 3;
                unsigned d = (unsigned)sm->rowch[p1][ly] | (unsigned)sm->rowch[p2][ly];
                if (ly > 0)        d |= (unsigned)sm->rowch[p1][ly - 1] | (unsigned)sm->rowch[p2][ly - 1];
                else if (pprev)    d |= (unsigned)pprev->rowch[p1][ROWS - 1] | (unsigned)pprev->rowch[p2][ROWS - 1];
                if (ly < ROWS - 1) d |= (unsigned)sm->rowch[p1][ly + 1] | (unsigned)sm->rowch[p2][ly + 1];
                else if (pnext)    d |= (unsigned)pnext->rowch[p1][0] | (unsigned)pnext->rowch[p2][0];
                recompute = (d != 0u);
            }
            uint32_t ch = 0;
            if (recompute) {
                const uint32_t* rA = (ly > 0) ? sm->img[0][ly - 1]
                                  : (pprev ? pprev->img[0][ROWS - 1] : sm->zero);
                const uint32_t* rB = (ly < ROWS - 1) ? sm->img[0][ly + 1]
                                  : (pnext ? pnext->img[0][0] : sm->zero);
                ch = thinN<0, NWRD>(rA, sm->img[0][ly], rB, sm->img[1][ly], w0);
            }
            unsigned bal = __ballot_sync(0xffffffffu, ch != 0u);
            if ((tid % TPR) == 0)
                sm->rowch[cur][ly] = (uint8_t)(((bal >> rowsh) & ROWMASK) ? 1 : 0);
            if (bal && lane == 0) sm->sflag = 1;
        }
        cluster.sync();
        cur = (cur + 1) % 3;

        // ---- substep 1: img[1] -> img[0] ----
        {
            bool recompute = true;
            if (iter > 0) {
                int p1 = (cur + 2) % 3, p2 = (cur + 1) % 3;
                unsigned d = (unsigned)sm->rowch[p1][ly] | (unsigned)sm->rowch[p2][ly];
                if (ly > 0)        d |= (unsigned)sm->rowch[p1][ly - 1] | (unsigned)sm->rowch[p2][ly - 1];
                else if (pprev)    d |= (unsigned)pprev->rowch[p1][ROWS - 1] | (unsigned)pprev->rowch[p2][ROWS - 1];
                if (ly < ROWS - 1) d |= (unsigned)sm->rowch[p1][ly + 1] | (unsigned)sm->rowch[p2][ly + 1];
                else if (pnext)    d |= (unsigned)pnext->rowch[p1][0] | (unsigned)pnext->rowch[p2][0];
                recompute = (d != 0u);
            }
            uint32_t ch = 0;
            if (recompute) {
                const uint32_t* rA = (ly > 0) ? sm->img[1][ly - 1]
                                  : (pprev ? pprev->img[1][ROWS - 1] : sm->zero);
                const uint32_t* rB = (ly < ROWS - 1) ? sm->img[1][ly + 1]
                                  : (pnext ? pnext->img[1][0] : sm->zero);
                ch = thinN<1, NWRD>(rA, sm->img[1][ly], rB, sm->img[0][ly], w0);
            }
            unsigned bal = __ballot_sync(0xffffffffu, ch != 0u);
            if ((tid % TPR) == 0)
                sm->rowch[cur][ly] = (uint8_t)(((bal >> rowsh) & ROWMASK) ? 1 : 0);
            if (bal && lane == 0) sm->sflag = 1;
        }
        __syncthreads();
        if (tid == 0 && sm->sflag) { atomicOr(&flag[iter], 1); __threadfence(); }
        cluster.sync();
        cur = (cur + 1) % 3;
        if (__ldcg(&flag[iter]) == 0) break;
    }

    // ---- fused endpoint extraction from img[0] ----
    {
        const uint32_t* rA = (ly > 0) ? sm->img[0][ly - 1]
                          : (pprev ? pprev->img[0][ROWS - 1] : sm->zero);
        const uint32_t* rB = (ly < ROWS - 1) ? sm->img[0][ly + 1]
                          : (pnext ? pnext->img[0][0] : sm->zero);
        endpointN<NWRD>(rA, sm->img[0][ly], rB, img, rank * ROWS + ly, w0);
    }
    cluster.sync();
}

// 16-CTA clusters, 512 threads, 4 words/thread (8 threads per row)
__global__ void __cluster_dims__(16, 1, 1) __launch_bounds__(512, 1)
k_thin16(const float* __restrict__ pred) {
    __shared__ ThinSmem<64> sm;
    thin_main<16, 64, 512, 8>(&sm, pred);
}

// Fallback: 8-CTA clusters, 512 threads, 8 words/thread (proven R5 layout)
__global__ void __cluster_dims__(8, 1, 1) __launch_bounds__(512, 1)
k_thin8(const float* __restrict__ pred) {
    __shared__ ThinSmem<128> sm;
    thin_main<8, 128, 512, 4>(&sm, pred);
}

// ---------------------------------------------------------------------------
// K2: weight + BCE with DECOUPLED layouts (round-11 proven version, unchanged)
// ---------------------------------------------------------------------------
#define FA3(a, b, c, s, cy) { uint32_t _x = (a) ^ (b); (s) = _x ^ (c); (cy) = ((a) & (b)) | ((c) & _x); }

__global__ void __launch_bounds__(256) k_loss(const float* __restrict__ pred,
                                              const float* __restrict__ targ,
                                              float* __restrict__ out) {
    const int tid = threadIdx.x;
    const int img = blockIdx.x >> 7;
    const int y0  = (blockIdx.x & 127) * 8;
    const uint32_t* C = &g_cbits[img][0][0];

    __shared__ uint32_t tile[16][WW + 1];
    __shared__ uint32_t splanes[256 * 9];
    #pragma unroll
    for (int k = 0; k < 2; ++k) {
        int idx = tid + k * 256;
        int sr = idx >> 5, sw = idx & 31;
        int gy = y0 - 4 + sr;
        tile[sr][sw] = (gy >= 0 && gy < HH) ? C[gy * WW + sw] : 0u;
    }
    __syncthreads();

    {
        const int w = tid & 31, lr = tid >> 5;
        uint32_t rlo[9], rhi[9], orAll = 0;
        #pragma unroll
        for (int d = 0; d < 9; ++d) {
            uint32_t M = tile[lr + d][w];
            uint32_t L = (w > 0)  ? tile[lr + d][w - 1] : 0u;
            uint32_t R = (w < 31) ? tile[lr + d][w + 1] : 0u;
            rlo[d] = (L >> 28) | (M << 4);
            rhi[d] = (M >> 28) | ((R & 0xFu) << 4);
            orAll |= rlo[d] | rhi[d];
        }
        uint32_t* P = &splanes[tid * 9];
        if (orAll) {
            uint32_t s1, c1, s2, c2, s3, c3, c4, s5, c5, c6;
            FA3(rlo[0], rlo[1], rlo[2], s1, c1);
            FA3(rlo[3], rlo[4], rlo[5], s2, c2);
            FA3(rlo[6], rlo[7], rlo[8], s3, c3);
            uint32_t S0l, S1l, S2l, S3l;
            FA3(s1, s2, s3, S0l, c4);
            FA3(c1, c2, c3, s5, c5);
            S1l = s5 ^ c4; c6 = s5 & c4;
            S2l = c5 ^ c6; S3l = c5 & c6;
            P[0] = S0l; P[1] = S1l; P[2] = S2l; P[3] = S3l;
            FA3(rhi[0], rhi[1], rhi[2], s1, c1);
            FA3(rhi[3], rhi[4], rhi[5], s2, c2);
            FA3(rhi[6], rhi[7], rhi[8], s3, c3);
            uint32_t S0h, S1h, S2h, S3h;
            FA3(s1, s2, s3, S0h, c4);
            FA3(c1, c2, c3, s5, c5);
            S1h = s5 ^ c4; c6 = s5 & c4;
            S2h = c5 ^ c6; S3h = c5 & c6;
            P[4] = S0h; P[5] = S1h; P[6] = S2h; P[7] = S3h;
        }
        P[8] = orAll;
    }
    __syncthreads();

    const float4* p4 = (const float4*)pred + (size_t)blockIdx.x * 2048;
    const float4* t4 = (const float4*)targ + (size_t)blockIdx.x * 2048;
    const int kbase = (tid & 7) * 4;
    float fsum = 0.0f;

    float4 pv = __ldcs(p4 + tid), tv = __ldcs(t4 + tid);
    #pragma unroll
    for (int p = 0; p < 8; ++p) {
        float4 pn, tn;
        if (p < 7) { pn = __ldcs(p4 + (p + 1) * 256 + tid); tn = __ldcs(t4 + (p + 1) * 256 + tid); }
        const uint32_t* P = &splanes[(p * 32 + (tid >> 3)) * 9];
        uint32_t cov = P[8];
        float pa[4] = {pv.x, pv.y, pv.z, pv.w};
        float ta[4] = {tv.x, tv.y, tv.z, tv.w};
        #pragma unroll
        for (int j = 0; j < 4; ++j) {
            float pp = pa[j], tt = ta[j];
            float Lb = -(tt * __logf(pp) + (1.0f - tt) * __logf(1.0f - pp));
            float Wt = 1.0f;
            if (cov) {
                int k = kbase + j;
                int nsum = __popc(__funnelshift_r(P[0], P[4], k) & 0x1FFu)
                         + (__popc(__funnelshift_r(P[1], P[5], k) & 0x1FFu) << 1)
                         + (__popc(__funnelshift_r(P[2], P[6], k) & 0x1FFu) << 2)
                         + (__popc(__funnelshift_r(P[3], P[7], k) & 0x1FFu) << 3);
                if (nsum) Wt = 60.0f * (float)nsum;
            }
            fsum += Wt * Lb;
        }
        pv = pn; tv = tn;
    }

    __shared__ double sd[256];
    sd[tid] = (double)fsum;
    __syncthreads();
    #pragma unroll
    for (int s = 128; s > 0; s >>= 1) {
        if (tid < s) sd[tid] += sd[tid + s];
        __syncthreads();
    }
    __shared__ int slast;
    if (tid == 0) {
        g_partial[blockIdx.x] = sd[0];
        __threadfence();
        slast = (atomicAdd(&g_count, 1) == (int)gridDim.x - 1);
    }
    __syncthreads();
    if (!slast) return;

    double v = __ldcg(&g_partial[tid]) + __ldcg(&g_partial[tid + 256])
             + __ldcg(&g_partial[tid + 512]) + __ldcg(&g_partial[tid + 768]);
    sd[tid] = v;
    __syncthreads();
    #pragma unroll
    for (int s = 128; s > 0; s >>= 1) {
        if (tid < s) sd[tid] += sd[tid + s];
        __syncthreads();
    }
    if (tid == 0) out[0] = (float)(sd[0] * (1.0 / ((double)IMGS * HH * WPX)));
}

// ---------------------------------------------------------------------------
extern "C" void kernel_launch(void* const* d_in, const int* in_sizes, int n_in,
                              void* d_out, int out_size) {
    (void)in_sizes; (void)n_in; (void)out_size;
    const float* pred = (const float*)d_in[0];
    const float* targ = (const float*)d_in[1];
    float* out = (float*)d_out;

    cudaError_t e = cudaFuncSetAttribute(
        (const void*)k_thin16, cudaFuncAttributeNonPortableClusterSizeAllowed, 1);
    if (e == cudaSuccess) {
        k_thin16<<<128, 512>>>(pred);
    } else {
        (void)cudaGetLastError();   // clear sticky error before capture continues
        k_thin8<<<64, 512>>>(pred);
    }

    k_loss<<<1024, 256>>>(pred, targ, out);
}

// round 14
// speedup vs baseline: 1.1299x; 1.0615x over previous
#include <cuda_runtime.h>
#include <cooperative_groups.h>
#include <cstdint>

namespace cg = cooperative_groups;

#define IMGS 8
#define HH 1024
#define WPX 1024
#define WW 32            // 32-bit words per row
#define WP 33            // padded row stride (bank-conflict-free)
#define MAXIT 64

// Static global scratch (no allocations allowed)
__device__ uint32_t g_cbits[IMGS][HH][WW];    // endpoint bits (1 MB)
__device__ int      g_flag[IMGS * MAXIT];     // per-image per-iteration changed flags
__device__ double   g_partial[1024];          // block partial sums
__device__ int      g_count;                  // finished-block counter for k_loss
__device__ float    g_sink;                   // keeps warm-kernel loads alive

// ---------------------------------------------------------------------------
// helpers
// ---------------------------------------------------------------------------
__device__ __forceinline__ uint32_t shW(uint32_t l, uint32_t m) {
    return __funnelshift_l(l, m, 1);     // west neighbor mask
}
__device__ __forceinline__ uint32_t shE(uint32_t m, uint32_t r) {
    return __funnelshift_r(m, r, 1);     // east neighbor mask
}

struct Bn4 { uint32_t n0, n1, n2, n3; };

__device__ __forceinline__ Bn4 bn8(uint32_t P2, uint32_t P3, uint32_t P4, uint32_t P5,
                                   uint32_t P6, uint32_t P7, uint32_t P8, uint32_t P9) {
    uint32_t s1 = P2 ^ P3 ^ P4, k1 = (P2 & P3) | (P4 & (P2 | P3));
    uint32_t s2 = P5 ^ P6 ^ P7, k2 = (P5 & P6) | (P7 & (P5 | P6));
    uint32_t s3 = s1 ^ s2 ^ P8, k3 = (s1 & s2) | (P8 & (s1 | s2));
    uint32_t n0 = s3 ^ P9,      k4 = s3 & P9;
    uint32_t s4 = k1 ^ k2 ^ k3, k5 = (k1 & k2) | (k3 & (k1 | k2));
    uint32_t n1 = s4 ^ k4,      k6 = s4 & k4;
    Bn4 r; r.n0 = n0; r.n1 = n1; r.n2 = k5 ^ k6; r.n3 = k5 & k6; return r;
}

template <int SUB>
__device__ __forceinline__ uint32_t thin_rows(const uint32_t* __restrict__ rowA,
                                              const uint32_t* __restrict__ rowC,
                                              const uint32_t* __restrict__ rowB,
                                              uint32_t* __restrict__ dst, int w0) {
    uint32_t a[10], c[10], b[10];
    #pragma unroll
    for (int i = 0; i < 10; ++i) {
        int w = w0 - 1 + i;
        bool ok = (w >= 0) && (w < WW);
        a[i] = ok ? rowA[w] : 0u;
        c[i] = ok ? rowC[w] : 0u;
        b[i] = ok ? rowB[w] : 0u;
    }
    uint32_t ch = 0;
    #pragma unroll
    for (int i = 0; i < 8; ++i) {
        uint32_t aL = a[i], aM = a[i + 1], aR = a[i + 2];
        uint32_t cL = c[i], cM = c[i + 1], cR = c[i + 2];
        uint32_t bL = b[i], bM = b[i + 1], bR = b[i + 2];
        uint32_t P2 = aM, P6 = bM;
        uint32_t P3 = shE(aM, aR), P4 = shE(cM, cR), P5 = shE(bM, bR);
        uint32_t P7 = shW(bL, bM), P8 = shW(cL, cM), P9 = shW(aL, aM);
        Bn4 n = bn8(P2, P3, P4, P5, P6, P7, P8, P9);
        uint32_t ge2 = n.n1 | n.n2 | n.n3;
        uint32_t ge7 = n.n3 | (n.n0 & n.n1 & n.n2);
        uint32_t condB = ge2 & ~ge7;
        uint32_t t, acc, multi;
        acc = ~P2 & P3; multi = 0u;
        t = ~P3 & P4; multi |= acc & t; acc |= t;
        t = ~P4 & P5; multi |= acc & t; acc |= t;
        t = ~P5 & P6; multi |= acc & t; acc |= t;
        t = ~P6 & P7; multi |= acc & t; acc |= t;
        t = ~P7 & P8; multi |= acc & t; acc |= t;
        t = ~P8 & P9; multi |= acc & t; acc |= t;
        t = ~P9 & P2; multi |= acc & t; acc |= t;
        uint32_t A1 = acc & ~multi;
        uint32_t e1, e2;
        if (SUB == 0) { e1 = ~(P2 & P4 & P6); e2 = ~(P4 & P6 & P8); }
        else          { e1 = ~(P2 & P4 & P8); e2 = ~(P2 & P6 & P8); }
        uint32_t rem = cM & condB & A1 & e1 & e2;
        dst[w0 + i] = cM ^ rem;
        ch |= rem;
    }
    return ch;
}

__device__ __forceinline__ void endpoint_rows(const uint32_t* __restrict__ rowA,
                                              const uint32_t* __restrict__ rowC,
                                              const uint32_t* __restrict__ rowB,
                                              int img, int gy, int w0) {
    uint32_t a[10], c[10], b[10];
    #pragma unroll
    for (int i = 0; i < 10; ++i) {
        int w = w0 - 1 + i;
        bool ok = (w >= 0) && (w < WW);
        a[i] = ok ? rowA[w] : 0u;
        c[i] = ok ? rowC[w] : 0u;
        b[i] = ok ? rowB[w] : 0u;
    }
    #pragma unroll
    for (int i = 0; i < 8; ++i) {
        uint32_t aL = a[i], aM = a[i + 1], aR = a[i + 2];
        uint32_t cL = c[i], cM = c[i + 1], cR = c[i + 2];
        uint32_t bL = b[i], bM = b[i + 1], bR = b[i + 2];
        uint32_t P2 = aM, P6 = bM;
        uint32_t P3 = shE(aM, aR), P4 = shE(cM, cR), P5 = shE(bM, bR);
        uint32_t P7 = shW(bL, bM), P8 = shW(cL, cM), P9 = shW(aL, aM);
        Bn4 n = bn8(P2, P3, P4, P5, P6, P7, P8, P9);
        g_cbits[img][gy][w0 + i] = cM & n.n0 & ~(n.n1 | n.n2 | n.n3);
    }
}

// ---------------------------------------------------------------------------
// SMEM-resident cluster thinning (proven round-5/round-11 code, unchanged)
// ---------------------------------------------------------------------------
template <int ROWS>
struct ThinSmem {
    uint32_t img[2][ROWS][WP];   // ping-pong tiles, padded stride
    uint32_t zero[WP];
    uint8_t  rowch[3][ROWS];     // rolling per-row change flags
    int      sflag;
};

template <int NC, int ROWS, int NTHR, typename SM>
__device__ void thin_main(SM* sm, const float* __restrict__ pred) {
    cg::cluster_group cluster = cg::this_cluster();
    const int tid  = threadIdx.x;
    const int lane = tid & 31;
    const int warp = tid >> 5;
    const int rank = (int)cluster.block_rank();
    const int img  = blockIdx.x / NC;
    int* flag = &g_flag[img * MAXIT];

    // ---- pack phase: threshold pred into sm->img[0] (float4 + shfl-OR) ----
    constexpr int NWARP = NTHR / 32;
    for (int r = warp; r < ROWS; r += NWARP) {
        const float4* row = (const float4*)(pred + ((size_t)img * HH + (size_t)rank * ROWS + r) * WPX);
        #pragma unroll
        for (int step = 0; step < 8; ++step) {
            float4 v = row[step * 32 + lane];
            uint32_t nib = (v.x >= 0.5f ? 1u : 0u) | (v.y >= 0.5f ? 2u : 0u)
                         | (v.z >= 0.5f ? 4u : 0u) | (v.w >= 0.5f ? 8u : 0u);
            uint32_t x = nib << (4 * (lane & 7));
            x |= __shfl_xor_sync(0xffffffffu, x, 1);
            x |= __shfl_xor_sync(0xffffffffu, x, 2);
            x |= __shfl_xor_sync(0xffffffffu, x, 4);
            if ((lane & 7) == 0) sm->img[0][r][step * 4 + (lane >> 3)] = x;
        }
    }
    if (tid < WP) sm->zero[tid] = 0u;
    if (rank == 0) { for (int i = tid; i < MAXIT; i += NTHR) flag[i] = 0; }
    if (blockIdx.x == 0 && tid == 0) g_count = 0;
    __threadfence();
    cluster.sync();

    SM* pprev = (rank > 0)      ? (SM*)cluster.map_shared_rank(sm, rank - 1) : nullptr;
    SM* pnext = (rank < NC - 1) ? (SM*)cluster.map_shared_rank(sm, rank + 1) : nullptr;

    const int ly = tid >> 2;
    const int w0 = (tid & 3) * 8;

    int cur = 0;
    for (int iter = 0; iter < MAXIT; ++iter) {
        if (tid == 0) sm->sflag = 0;
        __syncthreads();

        // ---- substep 0: img[0] -> img[1] ----
        {
            bool recompute = true;
            if (iter > 0) {
                int p1 = (cur + 2) % 3, p2 = (cur + 1) % 3;
                unsigned d = (unsigned)sm->rowch[p1][ly] | (unsigned)sm->rowch[p2][ly];
                if (ly > 0)        d |= (unsigned)sm->rowch[p1][ly - 1] | (unsigned)sm->rowch[p2][ly - 1];
                else if (pprev)    d |= (unsigned)pprev->rowch[p1][ROWS - 1] | (unsigned)pprev->rowch[p2][ROWS - 1];
                if (ly < ROWS - 1) d |= (unsigned)sm->rowch[p1][ly + 1] | (unsigned)sm->rowch[p2][ly + 1];
                else if (pnext)    d |= (unsigned)pnext->rowch[p1][0] | (unsigned)pnext->rowch[p2][0];
                recompute = (d != 0u);
            }
            uint32_t ch = 0;
            if (recompute) {
                const uint32_t* rA = (ly > 0) ? sm->img[0][ly - 1]
                                  : (pprev ? pprev->img[0][ROWS - 1] : sm->zero);
                const uint32_t* rB = (ly < ROWS - 1) ? sm->img[0][ly + 1]
                                  : (pnext ? pnext->img[0][0] : sm->zero);
                ch = thin_rows<0>(rA, sm->img[0][ly], rB, sm->img[1][ly], w0);
            }
            unsigned bal = __ballot_sync(0xffffffffu, ch != 0u);
            if ((tid & 3) == 0)
                sm->rowch[cur][ly] = (uint8_t)(((bal >> (lane & 28)) & 0xFu) ? 1 : 0);
            if (bal && lane == 0) sm->sflag = 1;
        }
        cluster.sync();
        cur = (cur + 1) % 3;

        // ---- substep 1: img[1] -> img[0] ----
        {
            bool recompute = true;
            if (iter > 0) {
                int p1 = (cur + 2) % 3, p2 = (cur + 1) % 3;
                unsigned d = (unsigned)sm->rowch[p1][ly] | (unsigned)sm->rowch[p2][ly];
                if (ly > 0)        d |= (unsigned)sm->rowch[p1][ly - 1] | (unsigned)sm->rowch[p2][ly - 1];
                else if (pprev)    d |= (unsigned)pprev->rowch[p1][ROWS - 1] | (unsigned)pprev->rowch[p2][ROWS - 1];
                if (ly < ROWS - 1) d |= (unsigned)sm->rowch[p1][ly + 1] | (unsigned)sm->rowch[p2][ly + 1];
                else if (pnext)    d |= (unsigned)pnext->rowch[p1][0] | (unsigned)pnext->rowch[p2][0];
                recompute = (d != 0u);
            }
            uint32_t ch = 0;
            if (recompute) {
                const uint32_t* rA = (ly > 0) ? sm->img[1][ly - 1]
                                  : (pprev ? pprev->img[1][ROWS - 1] : sm->zero);
                const uint32_t* rB = (ly < ROWS - 1) ? sm->img[1][ly + 1]
                                  : (pnext ? pnext->img[1][0] : sm->zero);
                ch = thin_rows<1>(rA, sm->img[1][ly], rB, sm->img[0][ly], w0);
            }
            unsigned bal = __ballot_sync(0xffffffffu, ch != 0u);
            if ((tid & 3) == 0)
                sm->rowch[cur][ly] = (uint8_t)(((bal >> (lane & 28)) & 0xFu) ? 1 : 0);
            if (bal && lane == 0) sm->sflag = 1;
        }
        __syncthreads();
        if (tid == 0 && sm->sflag) { atomicOr(&flag[iter], 1); __threadfence(); }
        cluster.sync();
        cur = (cur + 1) % 3;
        if (__ldcg(&flag[iter]) == 0) break;
    }

    // ---- fused endpoint extraction from img[0] ----
    {
        const uint32_t* rA = (ly > 0) ? sm->img[0][ly - 1]
                          : (pprev ? pprev->img[0][ROWS - 1] : sm->zero);
        const uint32_t* rB = (ly < ROWS - 1) ? sm->img[0][ly + 1]
                          : (pnext ? pnext->img[0][0] : sm->zero);
        endpoint_rows(rA, sm->img[0][ly], rB, img, rank * ROWS + ly, w0);
    }
    cluster.sync();
}

__global__ void __cluster_dims__(16, 1, 1) __launch_bounds__(256, 1)
k_thin16(const float* __restrict__ pred) {
    __shared__ ThinSmem<64> sm;
    thin_main<16, 64, 256>(&sm, pred);
}

__global__ void __cluster_dims__(8, 1, 1) __launch_bounds__(512, 1)
k_thin8(const float* __restrict__ pred) {
    __shared__ ThinSmem<128> sm;
    thin_main<8, 128, 512>(&sm, pred);
}

// ---------------------------------------------------------------------------
// Warm kernel: stream targ through L2 (default caching policy) during thin.
// Result is dead except for an unlikely-branch store that keeps loads alive.
// ---------------------------------------------------------------------------
__global__ void __launch_bounds__(256) k_warm(const float* __restrict__ targ) {
    int i = blockIdx.x * 256 + threadIdx.x;       // 262144 threads
    const float4* t4 = (const float4*)targ;
    float s = 0.0f;
    #pragma unroll
    for (int q = 0; q < 8; ++q)
    {
        float4 v = t4[(size_t)q * 262144 + i];
        s += v.x + v.y + v.z + v.w;
    }
    if (s == 123456789.0f) g_sink = s;
}

// ---------------------------------------------------------------------------
// K2: weight + BCE with DECOUPLED layouts (round-11 code; __ldcs removed so
// L2 keeps pred/targ resident across pack -> loss and replay -> replay)
// ---------------------------------------------------------------------------
#define FA3(a, b, c, s, cy) { uint32_t _x = (a) ^ (b); (s) = _x ^ (c); (cy) = ((a) & (b)) | ((c) & _x); }

__global__ void __launch_bounds__(256) k_loss(const float* __restrict__ pred,
                                              const float* __restrict__ targ,
                                              float* __restrict__ out) {
    const int tid = threadIdx.x;
    const int img = blockIdx.x >> 7;
    const int y0  = (blockIdx.x & 127) * 8;
    const uint32_t* C = &g_cbits[img][0][0];

    __shared__ uint32_t tile[16][WW + 1];
    __shared__ uint32_t splanes[256 * 9];
    #pragma unroll
    for (int k = 0; k < 2; ++k) {
        int idx = tid + k * 256;
        int sr = idx >> 5, sw = idx & 31;
        int gy = y0 - 4 + sr;
        tile[sr][sw] = (gy >= 0 && gy < HH) ? C[gy * WW + sw] : 0u;
    }
    __syncthreads();

    {
        const int w = tid & 31, lr = tid >> 5;
        uint32_t rlo[9], rhi[9], orAll = 0;
        #pragma unroll
        for (int d = 0; d < 9; ++d) {
            uint32_t M = tile[lr + d][w];
            uint32_t L = (w > 0)  ? tile[lr + d][w - 1] : 0u;
            uint32_t R = (w < 31) ? tile[lr + d][w + 1] : 0u;
            rlo[d] = (L >> 28) | (M << 4);
            rhi[d] = (M >> 28) | ((R & 0xFu) << 4);
            orAll |= rlo[d] | rhi[d];
        }
        uint32_t* P = &splanes[tid * 9];
        if (orAll) {
            uint32_t s1, c1, s2, c2, s3, c3, c4, s5, c5, c6;
            FA3(rlo[0], rlo[1], rlo[2], s1, c1);
            FA3(rlo[3], rlo[4], rlo[5], s2, c2);
            FA3(rlo[6], rlo[7], rlo[8], s3, c3);
            uint32_t S0l, S1l, S2l, S3l;
            FA3(s1, s2, s3, S0l, c4);
            FA3(c1, c2, c3, s5, c5);
            S1l = s5 ^ c4; c6 = s5 & c4;
            S2l = c5 ^ c6; S3l = c5 & c6;
            P[0] = S0l; P[1] = S1l; P[2] = S2l; P[3] = S3l;
            FA3(rhi[0], rhi[1], rhi[2], s1, c1);
            FA3(rhi[3], rhi[4], rhi[5], s2, c2);
            FA3(rhi[6], rhi[7], rhi[8], s3, c3);
            uint32_t S0h, S1h, S2h, S3h;
            FA3(s1, s2, s3, S0h, c4);
            FA3(c1, c2, c3, s5, c5);
            S1h = s5 ^ c4; c6 = s5 & c4;
            S2h = c5 ^ c6; S3h = c5 & c6;
            P[4] = S0h; P[5] = S1h; P[6] = S2h; P[7] = S3h;
        }
        P[8] = orAll;
    }
    __syncthreads();

    const float4* p4 = (const float4*)pred + (size_t)blockIdx.x * 2048;
    const float4* t4 = (const float4*)targ + (size_t)blockIdx.x * 2048;
    const int kbase = (tid & 7) * 4;
    float fsum = 0.0f;

    float4 pv = p4[tid], tv = t4[tid];
    #pragma unroll
    for (int p = 0; p < 8; ++p) {
        float4 pn, tn;
        if (p < 7) { pn = p4[(p + 1) * 256 + tid]; tn = t4[(p + 1) * 256 + tid]; }
        const uint32_t* P = &splanes[(p * 32 + (tid >> 3)) * 9];
        uint32_t cov = P[8];
        float pa[4] = {pv.x, pv.y, pv.z, pv.w};
        float ta[4] = {tv.x, tv.y, tv.z, tv.w};
        #pragma unroll
        for (int j = 0; j < 4; ++j) {
            float pp = pa[j], tt = ta[j];
            float Lb = -(tt * __logf(pp) + (1.0f - tt) * __logf(1.0f - pp));
            float Wt = 1.0f;
            if (cov) {
                int k = kbase + j;
                int nsum = __popc(__funnelshift_r(P[0], P[4], k) & 0x1FFu)
                         + (__popc(__funnelshift_r(P[1], P[5], k) & 0x1FFu) << 1)
                         + (__popc(__funnelshift_r(P[2], P[6], k) & 0x1FFu) << 2)
                         + (__popc(__funnelshift_r(P[3], P[7], k) & 0x1FFu) << 3);
                if (nsum) Wt = 60.0f * (float)nsum;
            }
            fsum += Wt * Lb;
        }
        pv = pn; tv = tn;
    }

    __shared__ double sd[256];
    sd[tid] = (double)fsum;
    __syncthreads();
    #pragma unroll
    for (int s = 128; s > 0; s >>= 1) {
        if (tid < s) sd[tid] += sd[tid + s];
        __syncthreads();
    }
    __shared__ int slast;
    if (tid == 0) {
        g_partial[blockIdx.x] = sd[0];
        __threadfence();
        slast = (atomicAdd(&g_count, 1) == (int)gridDim.x - 1);
    }
    __syncthreads();
    if (!slast) return;

    double v = __ldcg(&g_partial[tid]) + __ldcg(&g_partial[tid + 256])
             + __ldcg(&g_partial[tid + 512]) + __ldcg(&g_partial[tid + 768]);
    sd[tid] = v;
    __syncthreads();
    #pragma unroll
    for (int s = 128; s > 0; s >>= 1) {
        if (tid < s) sd[tid] += sd[tid + s];
        __syncthreads();
    }
    if (tid == 0) out[0] = (float)(sd[0] * (1.0 / ((double)IMGS * HH * WPX)));
}

// ---------------------------------------------------------------------------
extern "C" void kernel_launch(void* const* d_in, const int* in_sizes, int n_in,
                              void* d_out, int out_size) {
    (void)in_sizes; (void)n_in; (void)out_size;
    const float* pred = (const float*)d_in[0];
    const float* targ = (const float*)d_in[1];
    float* out = (float*)d_out;

    // One-time resource handles (work launched is identical every call)
    static cudaStream_t s2 = 0;
    static cudaEvent_t ev0 = 0, ev1 = 0;
    static int fork_ok = -1;
    if (fork_ok < 0) {
        fork_ok = (cudaStreamCreateWithFlags(&s2, cudaStreamNonBlocking) == cudaSuccess &&
                   cudaEventCreateWithFlags(&ev0, cudaEventDisableTiming) == cudaSuccess &&
                   cudaEventCreateWithFlags(&ev1, cudaEventDisableTiming) == cudaSuccess) ? 1 : 0;
        (void)cudaGetLastError();
    }

    cudaError_t e = cudaFuncSetAttribute(
        (const void*)k_thin16, cudaFuncAttributeNonPortableClusterSizeAllowed, 1);
    bool use16 = (e == cudaSuccess);
    if (!use16) (void)cudaGetLastError();

    if (fork_ok == 1) {
        cudaEventRecord(ev0, 0);
        cudaStreamWaitEvent(s2, ev0, 0);
        if (use16) k_thin16<<<128, 256>>>(pred);
        else       k_thin8<<<64, 512>>>(pred);
        k_warm<<<1024, 256, 0, s2>>>(targ);     // L2-warm targ under thin
        cudaEventRecord(ev1, s2);
        cudaStreamWaitEvent(0, ev1, 0);         // join
    } else {
        if (use16) k_thin16<<<128, 256>>>(pred);
        else       k_thin8<<<64, 512>>>(pred);
    }

    k_loss<<<1024, 256>>>(pred, targ, out);
}

// round 15
// speedup vs baseline: 1.2144x; 1.0747x over previous
#include <cuda_runtime.h>
#include <cooperative_groups.h>
#include <cstdint>

namespace cg = cooperative_groups;

#define IMGS 8
#define HH 1024
#define WPX 1024
#define WW 32            // 32-bit words per row
#define WP 33            // padded row stride (bank-conflict-free)
#define MAXIT 64

// Static global scratch (no allocations allowed)
__device__ uint32_t g_cbits[IMGS][HH][WW];    // endpoint bits (1 MB)
__device__ int      g_flag[IMGS * MAXIT];     // per-image per-iteration changed flags
__device__ double   g_partial[1024];          // block partial sums
__device__ int      g_count;                  // finished-block counter for k_loss

// ---------------------------------------------------------------------------
// helpers
// ---------------------------------------------------------------------------
__device__ __forceinline__ uint32_t shW(uint32_t l, uint32_t m) {
    return __funnelshift_l(l, m, 1);     // west neighbor mask
}
__device__ __forceinline__ uint32_t shE(uint32_t m, uint32_t r) {
    return __funnelshift_r(m, r, 1);     // east neighbor mask
}

struct Bn4 { uint32_t n0, n1, n2, n3; };

__device__ __forceinline__ Bn4 bn8(uint32_t P2, uint32_t P3, uint32_t P4, uint32_t P5,
                                   uint32_t P6, uint32_t P7, uint32_t P8, uint32_t P9) {
    uint32_t s1 = P2 ^ P3 ^ P4, k1 = (P2 & P3) | (P4 & (P2 | P3));
    uint32_t s2 = P5 ^ P6 ^ P7, k2 = (P5 & P6) | (P7 & (P5 | P6));
    uint32_t s3 = s1 ^ s2 ^ P8, k3 = (s1 & s2) | (P8 & (s1 | s2));
    uint32_t n0 = s3 ^ P9,      k4 = s3 & P9;
    uint32_t s4 = k1 ^ k2 ^ k3, k5 = (k1 & k2) | (k3 & (k1 | k2));
    uint32_t n1 = s4 ^ k4,      k6 = s4 & k4;
    Bn4 r; r.n0 = n0; r.n1 = n1; r.n2 = k5 ^ k6; r.n3 = k5 & k6; return r;
}

template <int SUB>
__device__ __forceinline__ uint32_t thin_rows(const uint32_t* __restrict__ rowA,
                                              const uint32_t* __restrict__ rowC,
                                              const uint32_t* __restrict__ rowB,
                                              uint32_t* __restrict__ dst, int w0) {
    uint32_t a[10], c[10], b[10];
    #pragma unroll
    for (int i = 0; i < 10; ++i) {
        int w = w0 - 1 + i;
        bool ok = (w >= 0) && (w < WW);
        a[i] = ok ? rowA[w] : 0u;
        c[i] = ok ? rowC[w] : 0u;
        b[i] = ok ? rowB[w] : 0u;
    }
    uint32_t ch = 0;
    #pragma unroll
    for (int i = 0; i < 8; ++i) {
        uint32_t aL = a[i], aM = a[i + 1], aR = a[i + 2];
        uint32_t cL = c[i], cM = c[i + 1], cR = c[i + 2];
        uint32_t bL = b[i], bM = b[i + 1], bR = b[i + 2];
        uint32_t P2 = aM, P6 = bM;
        uint32_t P3 = shE(aM, aR), P4 = shE(cM, cR), P5 = shE(bM, bR);
        uint32_t P7 = shW(bL, bM), P8 = shW(cL, cM), P9 = shW(aL, aM);
        Bn4 n = bn8(P2, P3, P4, P5, P6, P7, P8, P9);
        uint32_t ge2 = n.n1 | n.n2 | n.n3;
        uint32_t ge7 = n.n3 | (n.n0 & n.n1 & n.n2);
        uint32_t condB = ge2 & ~ge7;
        uint32_t t, acc, multi;
        acc = ~P2 & P3; multi = 0u;
        t = ~P3 & P4; multi |= acc & t; acc |= t;
        t = ~P4 & P5; multi |= acc & t; acc |= t;
        t = ~P5 & P6; multi |= acc & t; acc |= t;
        t = ~P6 & P7; multi |= acc & t; acc |= t;
        t = ~P7 & P8; multi |= acc & t; acc |= t;
        t = ~P8 & P9; multi |= acc & t; acc |= t;
        t = ~P9 & P2; multi |= acc & t; acc |= t;
        uint32_t A1 = acc & ~multi;
        uint32_t e1, e2;
        if (SUB == 0) { e1 = ~(P2 & P4 & P6); e2 = ~(P4 & P6 & P8); }
        else          { e1 = ~(P2 & P4 & P8); e2 = ~(P2 & P6 & P8); }
        uint32_t rem = cM & condB & A1 & e1 & e2;
        dst[w0 + i] = cM ^ rem;
        ch |= rem;
    }
    return ch;
}

__device__ __forceinline__ void endpoint_rows(const uint32_t* __restrict__ rowA,
                                              const uint32_t* __restrict__ rowC,
                                              const uint32_t* __restrict__ rowB,
                                              int img, int gy, int w0) {
    uint32_t a[10], c[10], b[10];
    #pragma unroll
    for (int i = 0; i < 10; ++i) {
        int w = w0 - 1 + i;
        bool ok = (w >= 0) && (w < WW);
        a[i] = ok ? rowA[w] : 0u;
        c[i] = ok ? rowC[w] : 0u;
        b[i] = ok ? rowB[w] : 0u;
    }
    #pragma unroll
    for (int i = 0; i < 8; ++i) {
        uint32_t aL = a[i], aM = a[i + 1], aR = a[i + 2];
        uint32_t cL = c[i], cM = c[i + 1], cR = c[i + 2];
        uint32_t bL = b[i], bM = b[i + 1], bR = b[i + 2];
        uint32_t P2 = aM, P6 = bM;
        uint32_t P3 = shE(aM, aR), P4 = shE(cM, cR), P5 = shE(bM, bR);
        uint32_t P7 = shW(bL, bM), P8 = shW(cL, cM), P9 = shW(aL, aM);
        Bn4 n = bn8(P2, P3, P4, P5, P6, P7, P8, P9);
        g_cbits[img][gy][w0 + i] = cM & n.n0 & ~(n.n1 | n.n2 | n.n3);
    }
}

// ---------------------------------------------------------------------------
// SMEM-resident cluster thinning (proven round-5/round-11 code, unchanged)
// ---------------------------------------------------------------------------
template <int ROWS>
struct ThinSmem {
    uint32_t img[2][ROWS][WP];   // ping-pong tiles, padded stride
    uint32_t zero[WP];
    uint8_t  rowch[3][ROWS];     // rolling per-row change flags
    int      sflag;
};

template <int NC, int ROWS, int NTHR, typename SM>
__device__ void thin_main(SM* sm, const float* __restrict__ pred) {
    cg::cluster_group cluster = cg::this_cluster();
    const int tid  = threadIdx.x;
    const int lane = tid & 31;
    const int warp = tid >> 5;
    const int rank = (int)cluster.block_rank();
    const int img  = blockIdx.x / NC;
    int* flag = &g_flag[img * MAXIT];

    // ---- pack phase: threshold pred into sm->img[0] (float4 + shfl-OR) ----
    constexpr int NWARP = NTHR / 32;
    for (int r = warp; r < ROWS; r += NWARP) {
        const float4* row = (const float4*)(pred + ((size_t)img * HH + (size_t)rank * ROWS + r) * WPX);
        #pragma unroll
        for (int step = 0; step < 8; ++step) {
            float4 v = row[step * 32 + lane];
            uint32_t nib = (v.x >= 0.5f ? 1u : 0u) | (v.y >= 0.5f ? 2u : 0u)
                         | (v.z >= 0.5f ? 4u : 0u) | (v.w >= 0.5f ? 8u : 0u);
            uint32_t x = nib << (4 * (lane & 7));
            x |= __shfl_xor_sync(0xffffffffu, x, 1);
            x |= __shfl_xor_sync(0xffffffffu, x, 2);
            x |= __shfl_xor_sync(0xffffffffu, x, 4);
            if ((lane & 7) == 0) sm->img[0][r][step * 4 + (lane >> 3)] = x;
        }
    }
    if (tid < WP) sm->zero[tid] = 0u;
    if (rank == 0) { for (int i = tid; i < MAXIT; i += NTHR) flag[i] = 0; }
    if (blockIdx.x == 0 && tid == 0) g_count = 0;
    __threadfence();
    cluster.sync();

    SM* pprev = (rank > 0)      ? (SM*)cluster.map_shared_rank(sm, rank - 1) : nullptr;
    SM* pnext = (rank < NC - 1) ? (SM*)cluster.map_shared_rank(sm, rank + 1) : nullptr;

    const int ly = tid >> 2;
    const int w0 = (tid & 3) * 8;

    int cur = 0;
    for (int iter = 0; iter < MAXIT; ++iter) {
        if (tid == 0) sm->sflag = 0;
        __syncthreads();

        // ---- substep 0: img[0] -> img[1] ----
        {
            bool recompute = true;
            if (iter > 0) {
                int p1 = (cur + 2) % 3, p2 = (cur + 1) % 3;
                unsigned d = (unsigned)sm->rowch[p1][ly] | (unsigned)sm->rowch[p2][ly];
                if (ly > 0)        d |= (unsigned)sm->rowch[p1][ly - 1] | (unsigned)sm->rowch[p2][ly - 1];
                else if (pprev)    d |= (unsigned)pprev->rowch[p1][ROWS - 1] | (unsigned)pprev->rowch[p2][ROWS - 1];
                if (ly < ROWS - 1) d |= (unsigned)sm->rowch[p1][ly + 1] | (unsigned)sm->rowch[p2][ly + 1];
                else if (pnext)    d |= (unsigned)pnext->rowch[p1][0] | (unsigned)pnext->rowch[p2][0];
                recompute = (d != 0u);
            }
            uint32_t ch = 0;
            if (recompute) {
                const uint32_t* rA = (ly > 0) ? sm->img[0][ly - 1]
                                  : (pprev ? pprev->img[0][ROWS - 1] : sm->zero);
                const uint32_t* rB = (ly < ROWS - 1) ? sm->img[0][ly + 1]
                                  : (pnext ? pnext->img[0][0] : sm->zero);
                ch = thin_rows<0>(rA, sm->img[0][ly], rB, sm->img[1][ly], w0);
            }
            unsigned bal = __ballot_sync(0xffffffffu, ch != 0u);
            if ((tid & 3) == 0)
                sm->rowch[cur][ly] = (uint8_t)(((bal >> (lane & 28)) & 0xFu) ? 1 : 0);
            if (bal && lane == 0) sm->sflag = 1;
        }
        cluster.sync();
        cur = (cur + 1) % 3;

        // ---- substep 1: img[1] -> img[0] ----
        {
            bool recompute = true;
            if (iter > 0) {
                int p1 = (cur + 2) % 3, p2 = (cur + 1) % 3;
                unsigned d = (unsigned)sm->rowch[p1][ly] | (unsigned)sm->rowch[p2][ly];
                if (ly > 0)        d |= (unsigned)sm->rowch[p1][ly - 1] | (unsigned)sm->rowch[p2][ly - 1];
                else if (pprev)    d |= (unsigned)pprev->rowch[p1][ROWS - 1] | (unsigned)pprev->rowch[p2][ROWS - 1];
                if (ly < ROWS - 1) d |= (unsigned)sm->rowch[p1][ly + 1] | (unsigned)sm->rowch[p2][ly + 1];
                else if (pnext)    d |= (unsigned)pnext->rowch[p1][0] | (unsigned)pnext->rowch[p2][0];
                recompute = (d != 0u);
            }
            uint32_t ch = 0;
            if (recompute) {
                const uint32_t* rA = (ly > 0) ? sm->img[1][ly - 1]
                                  : (pprev ? pprev->img[1][ROWS - 1] : sm->zero);
                const uint32_t* rB = (ly < ROWS - 1) ? sm->img[1][ly + 1]
                                  : (pnext ? pnext->img[1][0] : sm->zero);
                ch = thin_rows<1>(rA, sm->img[1][ly], rB, sm->img[0][ly], w0);
            }
            unsigned bal = __ballot_sync(0xffffffffu, ch != 0u);
            if ((tid & 3) == 0)
                sm->rowch[cur][ly] = (uint8_t)(((bal >> (lane & 28)) & 0xFu) ? 1 : 0);
            if (bal && lane == 0) sm->sflag = 1;
        }
        __syncthreads();
        if (tid == 0 && sm->sflag) { atomicOr(&flag[iter], 1); __threadfence(); }
        cluster.sync();
        cur = (cur + 1) % 3;
        if (__ldcg(&flag[iter]) == 0) break;
    }

    // ---- fused endpoint extraction from img[0] ----
    {
        const uint32_t* rA = (ly > 0) ? sm->img[0][ly - 1]
                          : (pprev ? pprev->img[0][ROWS - 1] : sm->zero);
        const uint32_t* rB = (ly < ROWS - 1) ? sm->img[0][ly + 1]
                          : (pnext ? pnext->img[0][0] : sm->zero);
        endpoint_rows(rA, sm->img[0][ly], rB, img, rank * ROWS + ly, w0);
    }
    cluster.sync();
}

__global__ void __cluster_dims__(16, 1, 1) __launch_bounds__(256, 1)
k_thin16(const float* __restrict__ pred) {
    __shared__ ThinSmem<64> sm;
    thin_main<16, 64, 256>(&sm, pred);
}

__global__ void __cluster_dims__(8, 1, 1) __launch_bounds__(512, 1)
k_thin8(const float* __restrict__ pred) {
    __shared__ ThinSmem<128> sm;
    thin_main<8, 128, 512>(&sm, pred);
}

// ---------------------------------------------------------------------------
// K2: weight + BCE with DECOUPLED layouts (round-11 proven code; single
// change: pred uses plain cached loads to exploit L2 residency from the
// pack phase, targ keeps __ldcs since it has no reuse).
// ---------------------------------------------------------------------------
#define FA3(a, b, c, s, cy) { uint32_t _x = (a) ^ (b); (s) = _x ^ (c); (cy) = ((a) & (b)) | ((c) & _x); }

__global__ void __launch_bounds__(256) k_loss(const float* __restrict__ pred,
                                              const float* __restrict__ targ,
                                              float* __restrict__ out) {
    const int tid = threadIdx.x;
    const int img = blockIdx.x >> 7;
    const int y0  = (blockIdx.x & 127) * 8;
    const uint32_t* C = &g_cbits[img][0][0];

    __shared__ uint32_t tile[16][WW + 1];
    __shared__ uint32_t splanes[256 * 9];
    #pragma unroll
    for (int k = 0; k < 2; ++k) {
        int idx = tid + k * 256;
        int sr = idx >> 5, sw = idx & 31;
        int gy = y0 - 4 + sr;
        tile[sr][sw] = (gy >= 0 && gy < HH) ? C[gy * WW + sw] : 0u;
    }
    __syncthreads();

    {
        const int w = tid & 31, lr = tid >> 5;
        uint32_t rlo[9], rhi[9], orAll = 0;
        #pragma unroll
        for (int d = 0; d < 9; ++d) {
            uint32_t M = tile[lr + d][w];
            uint32_t L = (w > 0)  ? tile[lr + d][w - 1] : 0u;
            uint32_t R = (w < 31) ? tile[lr + d][w + 1] : 0u;
            rlo[d] = (L >> 28) | (M << 4);
            rhi[d] = (M >> 28) | ((R & 0xFu) << 4);
            orAll |= rlo[d] | rhi[d];
        }
        uint32_t* P = &splanes[tid * 9];
        if (orAll) {
            uint32_t s1, c1, s2, c2, s3, c3, c4, s5, c5, c6;
            FA3(rlo[0], rlo[1], rlo[2], s1, c1);
            FA3(rlo[3], rlo[4], rlo[5], s2, c2);
            FA3(rlo[6], rlo[7], rlo[8], s3, c3);
            uint32_t S0l, S1l, S2l, S3l;
            FA3(s1, s2, s3, S0l, c4);
            FA3(c1, c2, c3, s5, c5);
            S1l = s5 ^ c4; c6 = s5 & c4;
            S2l = c5 ^ c6; S3l = c5 & c6;
            P[0] = S0l; P[1] = S1l; P[2] = S2l; P[3] = S3l;
            FA3(rhi[0], rhi[1], rhi[2], s1, c1);
            FA3(rhi[3], rhi[4], rhi[5], s2, c2);
            FA3(rhi[6], rhi[7], rhi[8], s3, c3);
            uint32_t S0h, S1h, S2h, S3h;
            FA3(s1, s2, s3, S0h, c4);
            FA3(c1, c2, c3, s5, c5);
            S1h = s5 ^ c4; c6 = s5 & c4;
            S2h = c5 ^ c6; S3h = c5 & c6;
            P[4] = S0h; P[5] = S1h; P[6] = S2h; P[7] = S3h;
        }
        P[8] = orAll;
    }
    __syncthreads();

    const float4* p4 = (const float4*)pred + (size_t)blockIdx.x * 2048;
    const float4* t4 = (const float4*)targ + (size_t)blockIdx.x * 2048;
    const int kbase = (tid & 7) * 4;
    float fsum = 0.0f;

    float4 pv = p4[tid], tv = __ldcs(t4 + tid);
    #pragma unroll
    for (int p = 0; p < 8; ++p) {
        float4 pn, tn;
        if (p < 7) { pn = p4[(p + 1) * 256 + tid]; tn = __ldcs(t4 + (p + 1) * 256 + tid); }
        const uint32_t* P = &splanes[(p * 32 + (tid >> 3)) * 9];
        uint32_t cov = P[8];
        float pa[4] = {pv.x, pv.y, pv.z, pv.w};
        float ta[4] = {tv.x, tv.y, tv.z, tv.w};
        #pragma unroll
        for (int j = 0; j < 4; ++j) {
            float pp = pa[j], tt = ta[j];
            float Lb = -(tt * __logf(pp) + (1.0f - tt) * __logf(1.0f - pp));
            float Wt = 1.0f;
            if (cov) {
                int k = kbase + j;
                int nsum = __popc(__funnelshift_r(P[0], P[4], k) & 0x1FFu)
                         + (__popc(__funnelshift_r(P[1], P[5], k) & 0x1FFu) << 1)
                         + (__popc(__funnelshift_r(P[2], P[6], k) & 0x1FFu) << 2)
                         + (__popc(__funnelshift_r(P[3], P[7], k) & 0x1FFu) << 3);
                if (nsum) Wt = 60.0f * (float)nsum;
            }
            fsum += Wt * Lb;
        }
        pv = pn; tv = tn;
    }

    __shared__ double sd[256];
    sd[tid] = (double)fsum;
    __syncthreads();
    #pragma unroll
    for (int s = 128; s > 0; s >>= 1) {
        if (tid < s) sd[tid] += sd[tid + s];
        __syncthreads();
    }
    __shared__ int slast;
    if (tid == 0) {
        g_partial[blockIdx.x] = sd[0];
        __threadfence();
        slast = (atomicAdd(&g_count, 1) == (int)gridDim.x - 1);
    }
    __syncthreads();
    if (!slast) return;

    double v = __ldcg(&g_partial[tid]) + __ldcg(&g_partial[tid + 256])
             + __ldcg(&g_partial[tid + 512]) + __ldcg(&g_partial[tid + 768]);
    sd[tid] = v;
    __syncthreads();
    #pragma unroll
    for (int s = 128; s > 0; s >>= 1) {
        if (tid < s) sd[tid] += sd[tid + s];
        __syncthreads();
    }
    if (tid == 0) out[0] = (float)(sd[0] * (1.0 / ((double)IMGS * HH * WPX)));
}

// ---------------------------------------------------------------------------
extern "C" void kernel_launch(void* const* d_in, const int* in_sizes, int n_in,
                              void* d_out, int out_size) {
    (void)in_sizes; (void)n_in; (void)out_size;
    const float* pred = (const float*)d_in[0];
    const float* targ = (const float*)d_in[1];
    float* out = (float*)d_out;

    cudaError_t e = cudaFuncSetAttribute(
        (const void*)k_thin16, cudaFuncAttributeNonPortableClusterSizeAllowed, 1);
    if (e == cudaSuccess) {
        k_thin16<<<128, 256>>>(pred);
    } else {
        (void)cudaGetLastError();   // clear sticky error before capture continues
        k_thin8<<<64, 512>>>(pred);
    }

    k_loss<<<1024, 256>>>(pred, targ, out);
}